// round 3
// baseline (speedup 1.0000x reference)
#include <cuda_runtime.h>

#define N 384
#define NN (N * N)
#define NLAYER 4
#define MAXSPLIT 8
#define KCHUNK 2048

// ---------------- device scratch (no allocations allowed) ----------------
__device__ float g_partial[NLAYER][MAXSPLIT][NN];  // split-K partial dot products
__device__ float g_norm[NLAYER][2 * N];            // [l][0..383]=|a_i|^2, [l][384..767]=|b_j|^2
__device__ float g_cost[NLAYER + 1][NN];           // 4 layer costs + combined (index 4)
__device__ int   g_assign[NLAYER + 1][N];          // col_of_row per LAP problem

// ---------------- row norms: one block per row ----------------
__global__ void norm_kernel(const float* __restrict__ base, int d, int layer) {
    int row = blockIdx.x;  // 0..767 (A rows then B rows, contiguous in [2,N,d])
    const float* p = base + (size_t)row * d;
    float s = 0.f;
    int t = threadIdx.x;
    const float4* p4 = (const float4*)p;
    int n4 = d >> 2;
    for (int k = t; k < n4; k += 256) {
        float4 x = p4[k];
        s += x.x * x.x + x.y * x.y + x.z * x.z + x.w * x.w;
    }
    __shared__ float red[8];
    for (int o = 16; o; o >>= 1) s += __shfl_down_sync(0xffffffffu, s, o);
    if ((t & 31) == 0) red[t >> 5] = s;
    __syncthreads();
    if (t < 8) {
        s = red[t];
        for (int o = 4; o; o >>= 1) s += __shfl_down_sync(0xffu, s, o);
        if (t == 0) g_norm[layer][row] = s;
    }
}

// ---------------- split-K NT GEMM: partial[s] = A_chunk @ B_chunk^T ----------------
// block: 256 threads, 64x64 tile, k-tile 16. grid (6, 6, nsplit)
__global__ __launch_bounds__(256) void gemm_kernel(const float* __restrict__ A,
                                                   const float* __restrict__ B,
                                                   int d, int layer) {
    __shared__ float As[16][64];
    __shared__ float Bs[16][64];
    int it = blockIdx.x * 64;
    int jt = blockIdx.y * 64;
    int s  = blockIdx.z;
    int kbase = s * KCHUNK;
    int t = threadIdx.x;
    int tx = t & 15, ty = t >> 4;

    float acc[4][4] = {};

    for (int kb = kbase; kb < kbase + KCHUNK; kb += 16) {
        __syncthreads();
#pragma unroll
        for (int e = 0; e < 4; e++) {
            int idx = t + e * 256;
            int li = idx >> 4, lk = idx & 15;
            As[lk][li] = A[(size_t)(it + li) * d + kb + lk];
            Bs[lk][li] = B[(size_t)(jt + li) * d + kb + lk];
        }
        __syncthreads();
#pragma unroll
        for (int kk = 0; kk < 16; kk++) {
            float4 a = *(const float4*)&As[kk][ty * 4];
            float4 b = *(const float4*)&Bs[kk][tx * 4];
            acc[0][0] += a.x * b.x; acc[0][1] += a.x * b.y; acc[0][2] += a.x * b.z; acc[0][3] += a.x * b.w;
            acc[1][0] += a.y * b.x; acc[1][1] += a.y * b.y; acc[1][2] += a.y * b.z; acc[1][3] += a.y * b.w;
            acc[2][0] += a.z * b.x; acc[2][1] += a.z * b.y; acc[2][2] += a.z * b.z; acc[2][3] += a.z * b.w;
            acc[3][0] += a.w * b.x; acc[3][1] += a.w * b.y; acc[3][2] += a.w * b.z; acc[3][3] += a.w * b.w;
        }
    }
    float* out = &g_partial[layer][s][0];
#pragma unroll
    for (int e = 0; e < 4; e++)
#pragma unroll
        for (int f = 0; f < 4; f++)
            out[(it + ty * 4 + e) * N + (jt + tx * 4 + f)] = acc[e][f];
}

// ---------------- epilogue: layer costs + combined, replicating reference rounding ----------------
__global__ void combine_kernel() {
    int idx = blockIdx.x * blockDim.x + threadIdx.x;
    if (idx >= NN) return;
    int i = idx / N, j = idx % N;
    const float w[4]    = {1.f, 0.5f, 0.25f, 0.125f};
    const int nsplit[4] = {8, 8, 4, 4};
    const float invd[4] = {1.f / 16384.f, 1.f / 16384.f, 1.f / 8192.f, 1.f / 8192.f};
    float comb = 0.f;
#pragma unroll
    for (int l = 0; l < 4; l++) {
        float dot = 0.f;
        for (int ss = 0; ss < nsplit[l]; ss++) dot += g_partial[l][ss][idx];
        // reference: clip(sqA - 2*dot + sqB, 0) / d   (2*dot exact, /d exact: both powers of 2)
        float sq = (g_norm[l][i] - 2.0f * dot) + g_norm[l][N + j];
        float c = fmaxf(sq, 0.f) * invd[l];
        g_cost[l][idx] = c;
        comb += w[l] * c;  // w[l]*c exact (power-of-2 weight) -> same rounding as reference add
    }
    g_cost[4][idx] = comb;
}

// ---------------- warp-synchronous Jonker-Volgenant LAP, one warp per problem ----------------
// Per-lane registerized column state: lane owns columns j = 1 + lane + 32*t, t in [0,12).
// v[], minv[] in registers, used as a 12-bit mask. Only u/p/way stay in shared.
// JV column-reduction init: v[j] = min_i C[i,j]; greedily assign argmin rows.
// Expected free rows after init ~= N/e (~141 of 384) -> ~2.5x fewer Dijkstra solves.
__global__ void lap_kernel() {
    const float* __restrict__ C = &g_cost[blockIdx.x][0];
    __shared__ float u[N + 1];
    __shared__ int p[N + 1], way[N + 1];
    __shared__ int cmrow[N + 1];    // argmin row per column (1-indexed)
    __shared__ int rowdone[N + 1];  // 1 if row already matched
    int lane = threadIdx.x;

    float v[12], minv[12];
    unsigned usedmask;

    for (int j = lane; j <= N; j += 32) { u[j] = 0.f; p[j] = 0; rowdone[j] = 0; }
    __syncwarp();

    // ---- column reduction: v[j] = min_i C[i-1][j-1], remember argmin row ----
#pragma unroll
    for (int t = 0; t < 12; t++) { v[t] = 3.0e38f; }
    int cmr[12];
#pragma unroll
    for (int t = 0; t < 12; t++) cmr[t] = 1;
    for (int i = 1; i <= N; i++) {
        const float* Crow = C + (size_t)(i - 1) * N;
        float c[12];
#pragma unroll
        for (int t = 0; t < 12; t++) c[t] = Crow[lane + 32 * t];
#pragma unroll
        for (int t = 0; t < 12; t++)
            if (c[t] < v[t]) { v[t] = c[t]; cmr[t] = i; }
    }
#pragma unroll
    for (int t = 0; t < 12; t++) cmrow[1 + lane + 32 * t] = cmr[t];
    __syncwarp();
    // greedy unique-row assignment (serial, lane 0): if argmin row free, match it
    if (lane == 0) {
        for (int j = 1; j <= N; j++) {
            int i = cmrow[j];
            if (!rowdone[i]) { rowdone[i] = 1; p[j] = i; }
        }
    }
    __syncwarp();

    // ---- augment free rows via shortest augmenting path ----
    for (int i = 1; i <= N; i++) {
        if (rowdone[i]) continue;  // matched in column reduction
#pragma unroll
        for (int t = 0; t < 12; t++) minv[t] = 3.0e38f;
        usedmask = 0u;
        if (lane == 0) p[0] = i;
        __syncwarp();
        int j0 = 0;
        while (true) {
            // mark j0 used (register mask; j0 is uniform across the warp)
            if (j0 > 0 && lane == ((j0 - 1) & 31)) usedmask |= 1u << ((j0 - 1) >> 5);
            int i0 = p[j0];
            float ui0 = u[i0];
            const float* Crow = C + (size_t)(i0 - 1) * N;
            // front-batched unconditional loads: MLP=12, each t is one coalesced 128B line
            float c[12];
#pragma unroll
            for (int t = 0; t < 12; t++) c[t] = Crow[lane + 32 * t];
            float best = 3.0e38f; int bestj = N + 1;
#pragma unroll
            for (int t = 0; t < 12; t++) {
                if (!((usedmask >> t) & 1u)) {
                    int j = 1 + lane + 32 * t;
                    float cur = c[t] - ui0 - v[t];
                    if (cur < minv[t]) { minv[t] = cur; way[j] = j0; }
                    // strict < keeps the smallest j within this lane (t ascending == j ascending)
                    if (minv[t] < best) { best = minv[t]; bestj = j; }
                }
            }
            // warp min-reduce with lowest-column tie-break
#pragma unroll
            for (int o = 16; o; o >>= 1) {
                float ob = __shfl_down_sync(0xffffffffu, best, o);
                int   oj = __shfl_down_sync(0xffffffffu, bestj, o);
                if (ob < best || (ob == best && oj < bestj)) { best = ob; bestj = oj; }
            }
            float delta = __shfl_sync(0xffffffffu, best, 0);
            int k = __shfl_sync(0xffffffffu, bestj, 0);
            // dual update: used cols -> u[p[j]] += delta (distinct rows, conflict-free), v -= delta
            //              unused    -> minv -= delta
#pragma unroll
            for (int t = 0; t < 12; t++) {
                if ((usedmask >> t) & 1u) {
                    int j = 1 + lane + 32 * t;
                    u[p[j]] += delta;
                    v[t] -= delta;
                } else {
                    minv[t] -= delta;
                }
            }
            if (lane == 0) u[p[0]] += delta;  // virtual column 0 is always "used": u[i] += delta
            __syncwarp();                      // publish u / way before next read
            j0 = k;
            if (p[j0] == 0) break;
        }
        // augment along way[] (lane 0)
        if (lane == 0) {
            rowdone[i] = 1;
            int jj = j0;
            while (jj) { int j1 = way[jj]; p[jj] = p[j1]; jj = j1; }
        }
        __syncwarp();
    }
    for (int j = 1 + lane; j <= N; j += 32) g_assign[blockIdx.x][p[j] - 1] = j - 1;
}

// ---------------- finalize: hamming total + index outputs ----------------
__global__ void finalize_kernel(const void* permA, const void* permB, float* out) {
    __shared__ int idealcol[N];
    __shared__ int match[4];
    __shared__ int is64;
    int t = threadIdx.x;  // 384 threads
    if (t == 0) {
        // detect int64 vs int32 perms: int64 little-endian -> every odd 32-bit word is 0
        const int* pa = (const int*)permA;
        int z = 1;
        for (int q = 1; q < 384; q += 2) if (pa[q] != 0) { z = 0; break; }
        is64 = z;
        match[0] = match[1] = match[2] = match[3] = 0;
    }
    __syncthreads();
    int a, b;
    if (is64) {
        a = (int)((const long long*)permA)[t];
        b = (int)((const long long*)permB)[t];
    } else {
        a = ((const int*)permA)[t];
        b = ((const int*)permB)[t];
    }
    idealcol[a] = b;
    __syncthreads();
    for (int l = 0; l < 4; l++)
        if (g_assign[l][t] == idealcol[t]) atomicAdd(&match[l], 1);
    __syncthreads();
    if (t == 0) {
        const float w[4] = {1.f, 0.5f, 0.25f, 0.125f};
        float total = 0.f;
        for (int l = 0; l < 4; l++)
            total += w[l] * (2.0f * (float)(N - match[l]) / (float)N);
        out[0] = total;
    }
    out[1 + t]     = (float)t;                  // row_ind
    out[1 + N + t] = (float)g_assign[4][t];     // col_ind from combined matrix
}

// ---------------- launch ----------------
extern "C" void kernel_launch(void* const* d_in, const int* in_sizes, int n_in,
                              void* d_out, int out_size) {
    const float* L[4] = {(const float*)d_in[0], (const float*)d_in[1],
                         (const float*)d_in[2], (const float*)d_in[3]};
    const int dims[4]   = {16384, 16384, 8192, 8192};
    const int nsplit[4] = {8, 8, 4, 4};

    for (int l = 0; l < 4; l++)
        norm_kernel<<<2 * N, 256>>>(L[l], dims[l], l);

    for (int l = 0; l < 4; l++) {
        const float* A = L[l];
        const float* B = L[l] + (size_t)N * dims[l];
        gemm_kernel<<<dim3(6, 6, nsplit[l]), 256>>>(A, B, dims[l], l);
    }

    combine_kernel<<<(NN + 255) / 256, 256>>>();

    lap_kernel<<<NLAYER + 1, 32>>>();

    finalize_kernel<<<1, N>>>(d_in[4], d_in[5], (float*)d_out);
}

// round 4
// speedup vs baseline: 2.1140x; 2.1140x over previous
#include <cuda_runtime.h>

#define N 384
#define NN (N * N)
#define NLAYER 4
#define MAXSPLIT 8
#define KCHUNK 2048

// ---------------- device scratch (no allocations allowed) ----------------
__device__ float g_partial[NLAYER][MAXSPLIT][NN];  // split-K partial dot products
__device__ float g_norm[NLAYER][2 * N];            // [l][0..383]=|a_i|^2, [l][384..767]=|b_j|^2
__device__ float g_cost[NLAYER + 1][NN];           // 4 layer costs + combined (index 4)
__device__ int   g_assign[NLAYER + 1][N];          // col_of_row per LAP problem

// ---------------- row norms: one block per row ----------------
__global__ void norm_kernel(const float* __restrict__ base, int d, int layer) {
    int row = blockIdx.x;  // 0..767 (A rows then B rows, contiguous in [2,N,d])
    const float* p = base + (size_t)row * d;
    float s = 0.f;
    int t = threadIdx.x;
    const float4* p4 = (const float4*)p;
    int n4 = d >> 2;
    for (int k = t; k < n4; k += 256) {
        float4 x = p4[k];
        s += x.x * x.x + x.y * x.y + x.z * x.z + x.w * x.w;
    }
    __shared__ float red[8];
    for (int o = 16; o; o >>= 1) s += __shfl_down_sync(0xffffffffu, s, o);
    if ((t & 31) == 0) red[t >> 5] = s;
    __syncthreads();
    if (t < 8) {
        s = red[t];
        for (int o = 4; o; o >>= 1) s += __shfl_down_sync(0xffu, s, o);
        if (t == 0) g_norm[layer][row] = s;
    }
}

// ---------------- split-K NT GEMM: partial[s] = A_chunk @ B_chunk^T ----------------
// block: 256 threads, 64x64 tile, k-tile 16. grid (6, 6, nsplit)
__global__ __launch_bounds__(256) void gemm_kernel(const float* __restrict__ A,
                                                   const float* __restrict__ B,
                                                   int d, int layer) {
    __shared__ float As[16][64];
    __shared__ float Bs[16][64];
    int it = blockIdx.x * 64;
    int jt = blockIdx.y * 64;
    int s  = blockIdx.z;
    int kbase = s * KCHUNK;
    int t = threadIdx.x;
    int tx = t & 15, ty = t >> 4;

    float acc[4][4] = {};

    for (int kb = kbase; kb < kbase + KCHUNK; kb += 16) {
        __syncthreads();
#pragma unroll
        for (int e = 0; e < 4; e++) {
            int idx = t + e * 256;
            int li = idx >> 4, lk = idx & 15;
            As[lk][li] = A[(size_t)(it + li) * d + kb + lk];
            Bs[lk][li] = B[(size_t)(jt + li) * d + kb + lk];
        }
        __syncthreads();
#pragma unroll
        for (int kk = 0; kk < 16; kk++) {
            float4 a = *(const float4*)&As[kk][ty * 4];
            float4 b = *(const float4*)&Bs[kk][tx * 4];
            acc[0][0] += a.x * b.x; acc[0][1] += a.x * b.y; acc[0][2] += a.x * b.z; acc[0][3] += a.x * b.w;
            acc[1][0] += a.y * b.x; acc[1][1] += a.y * b.y; acc[1][2] += a.y * b.z; acc[1][3] += a.y * b.w;
            acc[2][0] += a.z * b.x; acc[2][1] += a.z * b.y; acc[2][2] += a.z * b.z; acc[2][3] += a.z * b.w;
            acc[3][0] += a.w * b.x; acc[3][1] += a.w * b.y; acc[3][2] += a.w * b.z; acc[3][3] += a.w * b.w;
        }
    }
    float* out = &g_partial[layer][s][0];
#pragma unroll
    for (int e = 0; e < 4; e++)
#pragma unroll
        for (int f = 0; f < 4; f++)
            out[(it + ty * 4 + e) * N + (jt + tx * 4 + f)] = acc[e][f];
}

// ---------------- epilogue: layer costs + combined, replicating reference rounding ----------------
__global__ void combine_kernel() {
    int idx = blockIdx.x * blockDim.x + threadIdx.x;
    if (idx >= NN) return;
    int i = idx / N, j = idx % N;
    const float w[4]    = {1.f, 0.5f, 0.25f, 0.125f};
    const int nsplit[4] = {8, 8, 4, 4};
    const float invd[4] = {1.f / 16384.f, 1.f / 16384.f, 1.f / 8192.f, 1.f / 8192.f};
    float comb = 0.f;
#pragma unroll
    for (int l = 0; l < 4; l++) {
        float dot = 0.f;
        for (int ss = 0; ss < nsplit[l]; ss++) dot += g_partial[l][ss][idx];
        float sq = (g_norm[l][i] - 2.0f * dot) + g_norm[l][N + j];
        float c = fmaxf(sq, 0.f) * invd[l];
        g_cost[l][idx] = c;
        comb += w[l] * c;
    }
    g_cost[4][idx] = comb;
}

// order-preserving float->uint map (handles negatives from rounding noise)
__device__ __forceinline__ unsigned fkey(float x) {
    unsigned u = __float_as_uint(x);
    return u ^ (unsigned)(((int)u >> 31) | 0x80000000);
}

// ---------------- warp-synchronous LAPJV, one warp per problem ----------------
// Column state registerized per lane (12 columns each). Absolute-distance Dijkstra
// (scipy-lapjv style): no u[] array (u via complementary slackness from the loaded
// row), v[] updated once per augmentation, zero shared writes in the inner loop.
__global__ void lap_kernel() {
    const float* __restrict__ C = &g_cost[blockIdx.x][0];
    __shared__ int p[N + 1], way[N + 1];
    __shared__ int cmrow[N + 1];    // argmin row per column (1-indexed)
    __shared__ int rowdone[N + 1];  // 1 if row already matched
    int lane = threadIdx.x;

    float v[12], minv[12];
    unsigned usedmask;

    for (int j = lane; j <= N; j += 32) { p[j] = 0; rowdone[j] = 0; }
    __syncwarp();

    // ---- column reduction: v[j] = min_i C[i-1][j-1], greedy unique-row matching ----
    int cmr[12];
#pragma unroll
    for (int t = 0; t < 12; t++) { v[t] = 3.0e38f; cmr[t] = 1; }
    for (int i = 1; i <= N; i++) {
        const float* Crow = C + (size_t)(i - 1) * N;
        float c[12];
#pragma unroll
        for (int t = 0; t < 12; t++) c[t] = Crow[lane + 32 * t];
#pragma unroll
        for (int t = 0; t < 12; t++)
            if (c[t] < v[t]) { v[t] = c[t]; cmr[t] = i; }
    }
#pragma unroll
    for (int t = 0; t < 12; t++) cmrow[1 + lane + 32 * t] = cmr[t];
    __syncwarp();
    if (lane == 0) {
        for (int j = 1; j <= N; j++) {
            int i = cmrow[j];
            if (!rowdone[i]) { rowdone[i] = 1; p[j] = i; }
        }
    }
    __syncwarp();

    // ---- shortest augmenting path for each remaining free row ----
    for (int i = 1; i <= N; i++) {
        if (rowdone[i]) continue;
        if (lane == 0) p[0] = i;
        usedmask = 0u;
        {
            const float* Crow = C + (size_t)(i - 1) * N;
#pragma unroll
            for (int t = 0; t < 12; t++) {
                float cc = Crow[lane + 32 * t];
                minv[t] = cc - v[t];              // u[i] = 0 for free rows
                way[1 + lane + 32 * t] = 0;
            }
        }
        __syncwarp();

        float dfin;
        int k;
        while (true) {
            // lane-local argmin over unused columns (ascending t == ascending j: strict < keeps lowest j)
            unsigned long long key = ~0ull;
#pragma unroll
            for (int t = 0; t < 12; t++) {
                if (!((usedmask >> t) & 1u)) {
                    unsigned long long cand =
                        ((unsigned long long)fkey(minv[t]) << 32) | (unsigned)(1 + lane + 32 * t);
                    if (cand < key) key = cand;
                }
            }
            // warp min-reduce: min value, then lowest column index (== np.argmin)
#pragma unroll
            for (int o = 16; o; o >>= 1) {
                unsigned long long ok = __shfl_down_sync(0xffffffffu, key, o);
                if (ok < key) key = ok;
            }
            key = __shfl_sync(0xffffffffu, key, 0);
            k = (int)(unsigned)key;
            int t0 = (k - 1) >> 5;
            int owner = (k - 1) & 31;
            // popped distance = owner lane's minv[t0] (uniform t0 -> predicated select)
            float mt0 = 0.f, vt0 = 0.f;
#pragma unroll
            for (int t = 0; t < 12; t++)
                if (t == t0) { mt0 = minv[t]; vt0 = v[t]; }
            dfin = __shfl_sync(0xffffffffu, mt0, owner);
            if (lane == owner) usedmask |= 1u << t0;
            int i0 = p[k];                        // broadcast LDS, uniform
            if (i0 == 0) break;                   // reached a free column -> augment
            // relax through row i0; u[i0] = C[i0][k] - v[k] (complementary slackness)
            const float* Crow = C + (size_t)(i0 - 1) * N;
            float c[12];
#pragma unroll
            for (int t = 0; t < 12; t++) c[t] = Crow[lane + 32 * t];
            float cv = 0.f;
#pragma unroll
            for (int t = 0; t < 12; t++)
                if (t == t0) cv = c[t] - vt0;
            float ui0 = __shfl_sync(0xffffffffu, cv, owner);
            float base = dfin - ui0;
#pragma unroll
            for (int t = 0; t < 12; t++) {
                if (!((usedmask >> t) & 1u)) {
                    float h = base + (c[t] - v[t]);
                    if (h < minv[t]) { minv[t] = h; way[1 + lane + 32 * t] = k; }
                }
            }
            // no __syncwarp needed: inner loop has no cross-lane shared dependencies
        }
        // one-shot dual update: v[j] += d[j] - d_final for used columns
#pragma unroll
        for (int t = 0; t < 12; t++)
            if ((usedmask >> t) & 1u) v[t] += minv[t] - dfin;
        __syncwarp();  // publish way[] to lane 0
        if (lane == 0) {
            rowdone[i] = 1;
            int jj = k;
            while (jj) { int j1 = way[jj]; p[jj] = p[j1]; jj = j1; }
        }
        __syncwarp();  // publish p[] to all lanes
    }
    for (int j = 1 + lane; j <= N; j += 32) g_assign[blockIdx.x][p[j] - 1] = j - 1;
}

// ---------------- finalize: hamming total + index outputs ----------------
__global__ void finalize_kernel(const void* permA, const void* permB, float* out) {
    __shared__ int idealcol[N];
    __shared__ int match[4];
    __shared__ int is64;
    int t = threadIdx.x;  // 384 threads
    if (t == 0) {
        const int* pa = (const int*)permA;
        int z = 1;
        for (int q = 1; q < 384; q += 2) if (pa[q] != 0) { z = 0; break; }
        is64 = z;
        match[0] = match[1] = match[2] = match[3] = 0;
    }
    __syncthreads();
    int a, b;
    if (is64) {
        a = (int)((const long long*)permA)[t];
        b = (int)((const long long*)permB)[t];
    } else {
        a = ((const int*)permA)[t];
        b = ((const int*)permB)[t];
    }
    idealcol[a] = b;
    __syncthreads();
    for (int l = 0; l < 4; l++)
        if (g_assign[l][t] == idealcol[t]) atomicAdd(&match[l], 1);
    __syncthreads();
    if (t == 0) {
        const float w[4] = {1.f, 0.5f, 0.25f, 0.125f};
        float total = 0.f;
        for (int l = 0; l < 4; l++)
            total += w[l] * (2.0f * (float)(N - match[l]) / (float)N);
        out[0] = total;
    }
    out[1 + t]     = (float)t;                  // row_ind
    out[1 + N + t] = (float)g_assign[4][t];     // col_ind from combined matrix
}

// ---------------- launch ----------------
extern "C" void kernel_launch(void* const* d_in, const int* in_sizes, int n_in,
                              void* d_out, int out_size) {
    const float* L[4] = {(const float*)d_in[0], (const float*)d_in[1],
                         (const float*)d_in[2], (const float*)d_in[3]};
    const int dims[4]   = {16384, 16384, 8192, 8192};
    const int nsplit[4] = {8, 8, 4, 4};

    for (int l = 0; l < 4; l++)
        norm_kernel<<<2 * N, 256>>>(L[l], dims[l], l);

    for (int l = 0; l < 4; l++) {
        const float* A = L[l];
        const float* B = L[l] + (size_t)N * dims[l];
        gemm_kernel<<<dim3(6, 6, nsplit[l]), 256>>>(A, B, dims[l], l);
    }

    combine_kernel<<<(NN + 255) / 256, 256>>>();

    lap_kernel<<<NLAYER + 1, 32>>>();

    finalize_kernel<<<1, N>>>(d_in[4], d_in[5], (float*)d_out);
}

// round 5
// speedup vs baseline: 3.0637x; 1.4492x over previous
#include <cuda_runtime.h>

#define N 384
#define NN (N * N)
#define NLAYER 4
#define MAXSPLIT 8
#define KCHUNK 2048

// ---------------- device scratch (no allocations allowed) ----------------
__device__ float g_partial[NLAYER][MAXSPLIT][NN];  // split-K partial dot products
__device__ float g_norm[NLAYER][2 * N];            // [l][0..383]=|a_i|^2, [l][384..767]=|b_j|^2
__device__ float g_cost[NLAYER + 1][NN];           // 4 layer costs + combined (index 4)
__device__ int   g_assign[NLAYER + 1][N];          // col_of_row per LAP problem

// ---------------- row norms: one block per row ----------------
__global__ void norm_kernel(const float* __restrict__ base, int d, int layer) {
    int row = blockIdx.x;  // 0..767 (A rows then B rows, contiguous in [2,N,d])
    const float* p = base + (size_t)row * d;
    float s = 0.f;
    int t = threadIdx.x;
    const float4* p4 = (const float4*)p;
    int n4 = d >> 2;
    for (int k = t; k < n4; k += 256) {
        float4 x = p4[k];
        s += x.x * x.x + x.y * x.y + x.z * x.z + x.w * x.w;
    }
    __shared__ float red[8];
    for (int o = 16; o; o >>= 1) s += __shfl_down_sync(0xffffffffu, s, o);
    if ((t & 31) == 0) red[t >> 5] = s;
    __syncthreads();
    if (t < 8) {
        s = red[t];
        for (int o = 4; o; o >>= 1) s += __shfl_down_sync(0xffu, s, o);
        if (t == 0) g_norm[layer][row] = s;
    }
}

// ---------------- split-K NT GEMM: partial[s] = A_chunk @ B_chunk^T ----------------
__global__ __launch_bounds__(256) void gemm_kernel(const float* __restrict__ A,
                                                   const float* __restrict__ B,
                                                   int d, int layer) {
    __shared__ float As[16][64];
    __shared__ float Bs[16][64];
    int it = blockIdx.x * 64;
    int jt = blockIdx.y * 64;
    int s  = blockIdx.z;
    int kbase = s * KCHUNK;
    int t = threadIdx.x;
    int tx = t & 15, ty = t >> 4;

    float acc[4][4] = {};

    for (int kb = kbase; kb < kbase + KCHUNK; kb += 16) {
        __syncthreads();
#pragma unroll
        for (int e = 0; e < 4; e++) {
            int idx = t + e * 256;
            int li = idx >> 4, lk = idx & 15;
            As[lk][li] = A[(size_t)(it + li) * d + kb + lk];
            Bs[lk][li] = B[(size_t)(jt + li) * d + kb + lk];
        }
        __syncthreads();
#pragma unroll
        for (int kk = 0; kk < 16; kk++) {
            float4 a = *(const float4*)&As[kk][ty * 4];
            float4 b = *(const float4*)&Bs[kk][tx * 4];
            acc[0][0] += a.x * b.x; acc[0][1] += a.x * b.y; acc[0][2] += a.x * b.z; acc[0][3] += a.x * b.w;
            acc[1][0] += a.y * b.x; acc[1][1] += a.y * b.y; acc[1][2] += a.y * b.z; acc[1][3] += a.y * b.w;
            acc[2][0] += a.z * b.x; acc[2][1] += a.z * b.y; acc[2][2] += a.z * b.z; acc[2][3] += a.z * b.w;
            acc[3][0] += a.w * b.x; acc[3][1] += a.w * b.y; acc[3][2] += a.w * b.z; acc[3][3] += a.w * b.w;
        }
    }
    float* out = &g_partial[layer][s][0];
#pragma unroll
    for (int e = 0; e < 4; e++)
#pragma unroll
        for (int f = 0; f < 4; f++)
            out[(it + ty * 4 + e) * N + (jt + tx * 4 + f)] = acc[e][f];
}

// ---------------- epilogue: layer costs + combined ----------------
__global__ void combine_kernel() {
    int idx = blockIdx.x * blockDim.x + threadIdx.x;
    if (idx >= NN) return;
    int i = idx / N, j = idx % N;
    const float w[4]    = {1.f, 0.5f, 0.25f, 0.125f};
    const int nsplit[4] = {8, 8, 4, 4};
    const float invd[4] = {1.f / 16384.f, 1.f / 16384.f, 1.f / 8192.f, 1.f / 8192.f};
    float comb = 0.f;
#pragma unroll
    for (int l = 0; l < 4; l++) {
        float dot = 0.f;
        for (int ss = 0; ss < nsplit[l]; ss++) dot += g_partial[l][ss][idx];
        float sq = (g_norm[l][i] - 2.0f * dot) + g_norm[l][N + j];
        float c = fmaxf(sq, 0.f) * invd[l];
        g_cost[l][idx] = c;
        comb += w[l] * c;
    }
    g_cost[4][idx] = comb;
}

// order-preserving float->uint map
__device__ __forceinline__ unsigned fkey(float x) {
    unsigned u = __float_as_uint(x);
    return u ^ (unsigned)(((int)u >> 31) | 0x80000000);
}

// ---------------- warp-synchronous LAPJV (CR + ARR + SAP), one warp per problem --------
__global__ void lap_kernel() {
    const float* __restrict__ C = &g_cost[blockIdx.x][0];
    __shared__ int p[N + 1], way[N + 1];
    __shared__ int cmrow[N + 1];
    __shared__ int rowdone[N + 1];
    __shared__ int freelist[N];
    __shared__ int nf_sh;
    int lane = threadIdx.x;

    float v[12], minv[12];
    unsigned usedmask;

    for (int j = lane; j <= N; j += 32) { p[j] = 0; rowdone[j] = 0; }
    __syncwarp();

    // ---- phase 1: column reduction ----
    int cmr[12];
#pragma unroll
    for (int t = 0; t < 12; t++) { v[t] = 3.0e38f; cmr[t] = 1; }
    for (int i = 1; i <= N; i++) {
        const float* Crow = C + (size_t)(i - 1) * N;
        float c[12];
#pragma unroll
        for (int t = 0; t < 12; t++) c[t] = Crow[lane + 32 * t];
#pragma unroll
        for (int t = 0; t < 12; t++)
            if (c[t] < v[t]) { v[t] = c[t]; cmr[t] = i; }
    }
#pragma unroll
    for (int t = 0; t < 12; t++) cmrow[1 + lane + 32 * t] = cmr[t];
    __syncwarp();
    if (lane == 0) {
        for (int j = 1; j <= N; j++) {
            int i = cmrow[j];
            if (!rowdone[i]) { rowdone[i] = 1; p[j] = i; }
        }
        int nf = 0;
        for (int i = 1; i <= N; i++) if (!rowdone[i]) freelist[nf++] = i;
        nf_sh = nf;
    }
    __syncwarp();

    // ---- phase 2: augmenting row reduction (2 passes, LAPJV style) ----
    {
        int nf = nf_sh;
        int budget = 4096;  // hard safety cap; leftover rows go to Dijkstra
        for (int pass = 0; pass < 2 && nf > 0; pass++) {
            int f0 = nf, k = 0, f = 0;
            while (k < f0 && budget > 0) {
                budget--;
                int i = freelist[k]; k++;  // uniform broadcast read
                // min + second-min scan of reduced row costs
                const float* Crow = C + (size_t)(i - 1) * N;
                float m1 = 3.0e38f, m2 = 3.0e38f; int bj = 0;
#pragma unroll
                for (int t = 0; t < 12; t++) {
                    float r = Crow[lane + 32 * t] - v[t];
                    if (r < m1) { m2 = m1; m1 = r; bj = 1 + lane + 32 * t; }
                    else if (r < m2) m2 = r;
                }
#pragma unroll
                for (int o = 16; o; o >>= 1) {
                    float b1 = __shfl_down_sync(0xffffffffu, m1, o);
                    int   b_j = __shfl_down_sync(0xffffffffu, bj, o);
                    float b2 = __shfl_down_sync(0xffffffffu, m2, o);
                    if (b1 < m1 || (b1 == m1 && b_j < bj)) { m2 = fminf(m1, b2); m1 = b1; bj = b_j; }
                    else m2 = fminf(m2, b1);
                }
                m1 = __shfl_sync(0xffffffffu, m1, 0);
                m2 = __shfl_sync(0xffffffffu, m2, 0);
                int j1 = __shfl_sync(0xffffffffu, bj, 0);
                int i1 = p[j1];
                int t0 = (j1 - 1) >> 5, owner = (j1 - 1) & 31;
                int prog = 0;
                if (m1 < m2) {
                    if (lane == owner) {
#pragma unroll
                        for (int t = 0; t < 12; t++)
                            if (t == t0) {
                                float nv = v[t] - (m2 - m1);
                                if (nv < v[t]) { v[t] = nv; prog = 1; }  // strict float progress
                            }
                    }
                    prog = __shfl_sync(0xffffffffu, prog, owner);
                }
                if (prog || i1 == 0) {
                    if (lane == 0) p[j1] = i;          // assign i -> j1 (kicks i1 if present)
                    if (i1 != 0 && prog) {
                        k--;                            // immediate reprocess of kicked row
                        if (lane == 0) freelist[k] = i1;
                    }
                } else {
                    if (lane == 0) freelist[f] = i;     // tie / no-progress: defer to next pass
                    f++;
                }
                __syncwarp();
            }
            nf = f;
        }
    }
    // recompute free rows from p[] (robust to ARR early exit / budget)
    for (int x = lane; x <= N; x += 32) rowdone[x] = 0;
    __syncwarp();
    for (int j = 1 + lane; j <= N; j += 32) { int r = p[j]; if (r) rowdone[r] = 1; }
    __syncwarp();

    // ---- phase 3: shortest augmenting path for remaining free rows ----
    for (int i = 1; i <= N; i++) {
        if (rowdone[i]) continue;
        if (lane == 0) p[0] = i;
        usedmask = 0u;
        {
            const float* Crow = C + (size_t)(i - 1) * N;
#pragma unroll
            for (int t = 0; t < 12; t++) {
                float cc = Crow[lane + 32 * t];
                minv[t] = cc - v[t];              // u[i] = 0 for free rows
                way[1 + lane + 32 * t] = 0;
            }
        }
        __syncwarp();

        float dfin;
        int k;
        while (true) {
            unsigned long long key = ~0ull;
#pragma unroll
            for (int t = 0; t < 12; t++) {
                if (!((usedmask >> t) & 1u)) {
                    unsigned long long cand =
                        ((unsigned long long)fkey(minv[t]) << 32) | (unsigned)(1 + lane + 32 * t);
                    if (cand < key) key = cand;
                }
            }
#pragma unroll
            for (int o = 16; o; o >>= 1) {
                unsigned long long ok = __shfl_down_sync(0xffffffffu, key, o);
                if (ok < key) key = ok;
            }
            key = __shfl_sync(0xffffffffu, key, 0);
            k = (int)(unsigned)key;
            int t0 = (k - 1) >> 5;
            int owner = (k - 1) & 31;
            float mt0 = 0.f, vt0 = 0.f;
#pragma unroll
            for (int t = 0; t < 12; t++)
                if (t == t0) { mt0 = minv[t]; vt0 = v[t]; }
            dfin = __shfl_sync(0xffffffffu, mt0, owner);
            if (lane == owner) usedmask |= 1u << t0;
            int i0 = p[k];
            if (i0 == 0) break;
            const float* Crow = C + (size_t)(i0 - 1) * N;
            float c[12];
#pragma unroll
            for (int t = 0; t < 12; t++) c[t] = Crow[lane + 32 * t];
            float cv = 0.f;
#pragma unroll
            for (int t = 0; t < 12; t++)
                if (t == t0) cv = c[t] - vt0;
            float ui0 = __shfl_sync(0xffffffffu, cv, owner);
            float base = dfin - ui0;
#pragma unroll
            for (int t = 0; t < 12; t++) {
                if (!((usedmask >> t) & 1u)) {
                    float h = base + (c[t] - v[t]);
                    if (h < minv[t]) { minv[t] = h; way[1 + lane + 32 * t] = k; }
                }
            }
        }
#pragma unroll
        for (int t = 0; t < 12; t++)
            if ((usedmask >> t) & 1u) v[t] += minv[t] - dfin;
        __syncwarp();
        if (lane == 0) {
            int jj = k;
            while (jj) { int j1 = way[jj]; p[jj] = p[j1]; jj = j1; }
        }
        __syncwarp();
    }
    for (int j = 1 + lane; j <= N; j += 32) g_assign[blockIdx.x][p[j] - 1] = j - 1;
}

// ---------------- finalize: hamming total + index outputs ----------------
__global__ void finalize_kernel(const void* permA, const void* permB, float* out) {
    __shared__ int idealcol[N];
    __shared__ int match[4];
    __shared__ int is64;
    int t = threadIdx.x;  // 384 threads
    if (t == 0) {
        const int* pa = (const int*)permA;
        int z = 1;
        for (int q = 1; q < 384; q += 2) if (pa[q] != 0) { z = 0; break; }
        is64 = z;
        match[0] = match[1] = match[2] = match[3] = 0;
    }
    __syncthreads();
    int a, b;
    if (is64) {
        a = (int)((const long long*)permA)[t];
        b = (int)((const long long*)permB)[t];
    } else {
        a = ((const int*)permA)[t];
        b = ((const int*)permB)[t];
    }
    idealcol[a] = b;
    __syncthreads();
    for (int l = 0; l < 4; l++)
        if (g_assign[l][t] == idealcol[t]) atomicAdd(&match[l], 1);
    __syncthreads();
    if (t == 0) {
        const float w[4] = {1.f, 0.5f, 0.25f, 0.125f};
        float total = 0.f;
        for (int l = 0; l < 4; l++)
            total += w[l] * (2.0f * (float)(N - match[l]) / (float)N);
        out[0] = total;
    }
    out[1 + t]     = (float)t;                  // row_ind
    out[1 + N + t] = (float)g_assign[4][t];     // col_ind from combined matrix
}

// ---------------- launch ----------------
extern "C" void kernel_launch(void* const* d_in, const int* in_sizes, int n_in,
                              void* d_out, int out_size) {
    const float* L[4] = {(const float*)d_in[0], (const float*)d_in[1],
                         (const float*)d_in[2], (const float*)d_in[3]};
    const int dims[4]   = {16384, 16384, 8192, 8192};
    const int nsplit[4] = {8, 8, 4, 4};

    for (int l = 0; l < 4; l++)
        norm_kernel<<<2 * N, 256>>>(L[l], dims[l], l);

    for (int l = 0; l < 4; l++) {
        const float* A = L[l];
        const float* B = L[l] + (size_t)N * dims[l];
        gemm_kernel<<<dim3(6, 6, nsplit[l]), 256>>>(A, B, dims[l], l);
    }

    combine_kernel<<<(NN + 255) / 256, 256>>>();

    lap_kernel<<<NLAYER + 1, 32>>>();

    finalize_kernel<<<1, N>>>(d_in[4], d_in[5], (float*)d_out);
}

// round 14
// speedup vs baseline: 3.8960x; 1.2717x over previous
#include <cuda_runtime.h>

#define N 384
#define NN (N * N)
#define NLAYER 4
#define MAXSPLIT 8
#define KCHUNK 2048
#define FULLW 0xffffffffu

// ---------------- device scratch (no allocations allowed) ----------------
__device__ float g_partial[NLAYER][MAXSPLIT][NN];  // split-K partial dot products
__device__ float g_norm[NLAYER][2 * N];            // [l][0..383]=|a_i|^2, [l][384..767]=|b_j|^2
__device__ float g_cost[NLAYER + 1][NN];           // 4 layer costs + combined (index 4)
__device__ int   g_assign[NLAYER + 1][N];          // col_of_row per LAP problem

// ---------------- row norms: one block per row, grid.y = layer within pair ----------------
__global__ void norm_kernel(const float* __restrict__ base0, const float* __restrict__ base1,
                            int d, int layer0) {
    int row = blockIdx.x;  // 0..767 (A rows then B rows, contiguous in [2,N,d])
    const float* base = blockIdx.y ? base1 : base0;
    int layer = layer0 + blockIdx.y;
    const float* p = base + (size_t)row * d;
    float s = 0.f;
    int t = threadIdx.x;
    const float4* p4 = (const float4*)p;
    int n4 = d >> 2;
    for (int k = t; k < n4; k += 256) {
        float4 x = p4[k];
        s += x.x * x.x + x.y * x.y + x.z * x.z + x.w * x.w;
    }
    __shared__ float red[8];
    for (int o = 16; o; o >>= 1) s += __shfl_down_sync(FULLW, s, o);
    if ((t & 31) == 0) red[t >> 5] = s;
    __syncthreads();
    if (t < 8) {
        s = red[t];
        for (int o = 4; o; o >>= 1) s += __shfl_down_sync(0xffu, s, o);
        if (t == 0) g_norm[layer][row] = s;
    }
}

// ---------------- split-K NT GEMM: partial[s] = A_chunk @ B_chunk^T ----------------
// block: 256 threads, 64x64 tile, k-tile 16. grid (6, 6, nsplit*2): z = split + nsplit*pair_member
__global__ __launch_bounds__(256) void gemm_kernel(const float* __restrict__ L0,
                                                   const float* __restrict__ L1,
                                                   int d, int nsplit, int layer0) {
    __shared__ float As[16][64];
    __shared__ float Bs[16][64];
    int it = blockIdx.x * 64;
    int jt = blockIdx.y * 64;
    int zm = blockIdx.z / nsplit;      // 0 or 1: which layer of the pair
    int s  = blockIdx.z % nsplit;
    int layer = layer0 + zm;
    const float* Lbase = zm ? L1 : L0;
    const float* A = Lbase;
    const float* B = Lbase + (size_t)N * d;
    int kbase = s * KCHUNK;
    int t = threadIdx.x;
    int tx = t & 15, ty = t >> 4;

    float acc[4][4] = {};

    for (int kb = kbase; kb < kbase + KCHUNK; kb += 16) {
        __syncthreads();
#pragma unroll
        for (int e = 0; e < 4; e++) {
            int idx = t + e * 256;
            int li = idx >> 4, lk = idx & 15;
            As[lk][li] = A[(size_t)(it + li) * d + kb + lk];
            Bs[lk][li] = B[(size_t)(jt + li) * d + kb + lk];
        }
        __syncthreads();
#pragma unroll
        for (int kk = 0; kk < 16; kk++) {
            float4 a = *(const float4*)&As[kk][ty * 4];
            float4 b = *(const float4*)&Bs[kk][tx * 4];
            acc[0][0] += a.x * b.x; acc[0][1] += a.x * b.y; acc[0][2] += a.x * b.z; acc[0][3] += a.x * b.w;
            acc[1][0] += a.y * b.x; acc[1][1] += a.y * b.y; acc[1][2] += a.y * b.z; acc[1][3] += a.y * b.w;
            acc[2][0] += a.z * b.x; acc[2][1] += a.z * b.y; acc[2][2] += a.z * b.z; acc[2][3] += a.z * b.w;
            acc[3][0] += a.w * b.x; acc[3][1] += a.w * b.y; acc[3][2] += a.w * b.z; acc[3][3] += a.w * b.w;
        }
    }
    float* out = &g_partial[layer][s][0];
#pragma unroll
    for (int e = 0; e < 4; e++)
#pragma unroll
        for (int f = 0; f < 4; f++)
            out[(it + ty * 4 + e) * N + (jt + tx * 4 + f)] = acc[e][f];
}

// ---------------- epilogue: layer costs + combined ----------------
__global__ void combine_kernel() {
    int idx = blockIdx.x * blockDim.x + threadIdx.x;
    if (idx >= NN) return;
    int i = idx / N, j = idx % N;
    const float w[4]    = {1.f, 0.5f, 0.25f, 0.125f};
    const int nsplit[4] = {8, 8, 4, 4};
    const float invd[4] = {1.f / 16384.f, 1.f / 16384.f, 1.f / 8192.f, 1.f / 8192.f};
    float comb = 0.f;
#pragma unroll
    for (int l = 0; l < 4; l++) {
        float dot = 0.f;
        for (int ss = 0; ss < nsplit[l]; ss++) dot += g_partial[l][ss][idx];
        float sq = (g_norm[l][i] - 2.0f * dot) + g_norm[l][N + j];
        float c = fmaxf(sq, 0.f) * invd[l];
        g_cost[l][idx] = c;
        comb += w[l] * c;
    }
    g_cost[4][idx] = comb;
}

// order-preserving bijective float<->uint maps
__device__ __forceinline__ unsigned fkey(float x) {
    unsigned u = __float_as_uint(x);
    return u ^ (unsigned)(((int)u >> 31) | 0x80000000);
}
__device__ __forceinline__ float unfkey(unsigned k) {
    unsigned m = (unsigned)(~((int)k >> 31)) | 0x80000000u;
    return __uint_as_float(k ^ m);
}

// load 12 contiguous floats (48B, 16B-aligned) as 3 float4
__device__ __forceinline__ void load_row12(const float* __restrict__ Crow, int jbase, float c[12]) {
    const float4* r4 = (const float4*)(Crow + jbase);
    float4 a = r4[0], b = r4[1], d = r4[2];
    c[0] = a.x; c[1] = a.y; c[2]  = a.z; c[3]  = a.w;
    c[4] = b.x; c[5] = b.y; c[6]  = b.z; c[7]  = b.w;
    c[8] = d.x; c[9] = d.y; c[10] = d.z; c[11] = d.w;
}

// ---------------- warp-synchronous LAPJV (CR + RT + ARR + SAP), one warp/problem -----
// Lane owns 12 CONTIGUOUS columns j = 1 + 12*lane + q  (lowest tied lane == lowest j).
__global__ void lap_kernel() {
    const float* __restrict__ C = &g_cost[blockIdx.x][0];
    __shared__ int p[N + 1], way[N + 1];
    __shared__ int cmrow[N + 1];
    __shared__ int rowdone[N + 1];
    __shared__ int freelist[N];
    __shared__ int nf_sh;
    int lane = threadIdx.x;
    int jbase = lane * 12;

    float v[12], minv[12], c[12];
    unsigned usedmask;

    for (int j = lane; j <= N; j += 32) { p[j] = 0; rowdone[j] = 0; }
    __syncwarp();

    // ---- phase 1: column reduction ----
    int cmr[12];
#pragma unroll
    for (int q = 0; q < 12; q++) { v[q] = 3.0e38f; cmr[q] = 1; }
    for (int i = 1; i <= N; i++) {
        load_row12(C + (size_t)(i - 1) * N, jbase, c);
#pragma unroll
        for (int q = 0; q < 12; q++)
            if (c[q] < v[q]) { v[q] = c[q]; cmr[q] = i; }
    }
#pragma unroll
    for (int q = 0; q < 12; q++) cmrow[1 + jbase + q] = cmr[q];
    __syncwarp();
    if (lane == 0) {
        for (int j = 1; j <= N; j++) {
            int i = cmrow[j];
            if (!rowdone[i]) { rowdone[i] = 1; p[j] = i; }
        }
        int nf = 0;
        for (int i = 1; i <= N; i++) if (!rowdone[i]) freelist[nf++] = i;
        nf_sh = nf;
    }
    __syncwarp();

    // ---- phase 1b: reduction transfer (tighten v for assigned rows) ----
    // v_new[j] = C[i][j] - min_{j'!=j}(C[i][j'] - v[j']); keeps feasibility
    // (v only decreases) and complementary slackness equality at (i,j).
    for (int j = 1; j <= N; j++) {
        int i = p[j];  // uniform broadcast LDS
        if (i == 0) continue;
        load_row12(C + (size_t)(i - 1) * N, jbase, c);
        int ownerj = (j - 1) / 12, qj = (j - 1) % 12;
        float m = 3.0e38f;
#pragma unroll
        for (int q = 0; q < 12; q++) {
            float r = c[q] - v[q];
            if (!(lane == ownerj && q == qj) && r < m) m = r;
        }
        unsigned kmin = __reduce_min_sync(FULLW, fkey(m));
        float u2 = unfkey(kmin);
        if (lane == ownerj) {
#pragma unroll
            for (int q = 0; q < 12; q++)
                if (q == qj) v[q] = c[q] - u2;
        }
    }
    __syncwarp();

    // ---- phase 2: augmenting row reduction (2 passes) ----
    {
        int nf = nf_sh;
        int budget = 4096;
        for (int pass = 0; pass < 2 && nf > 0; pass++) {
            int f0 = nf, k = 0, f = 0;
            while (k < f0 && budget > 0) {
                budget--;
                int i = freelist[k]; k++;
                load_row12(C + (size_t)(i - 1) * N, jbase, c);
                float m1 = 3.0e38f, m2 = 3.0e38f; int bq = 0;
#pragma unroll
                for (int q = 0; q < 12; q++) {
                    float r = c[q] - v[q];
                    if (r < m1) { m2 = m1; m1 = r; bq = q; }
                    else if (r < m2) m2 = r;
                }
                unsigned k1 = __reduce_min_sync(FULLW, fkey(m1));
                unsigned ball = __ballot_sync(FULLW, fkey(m1) == k1);
                int src = __ffs(ball) - 1;                      // lowest lane == lowest j
                unsigned cand2 = (lane == src) ? fkey(m2) : fkey(m1);
                unsigned k2 = __reduce_min_sync(FULLW, cand2);
                float M1 = unfkey(k1), M2 = unfkey(k2);
                int j1 = __shfl_sync(FULLW, 1 + jbase + bq, src);
                int i1 = p[j1];
                int prog = 0;
                if (M1 < M2 && lane == src) {
#pragma unroll
                    for (int q = 0; q < 12; q++)
                        if (q == bq) {
                            float nv = v[q] - (M2 - M1);
                            if (nv < v[q]) { v[q] = nv; prog = 1; }  // strict float progress
                        }
                }
                prog = __shfl_sync(FULLW, prog, src);
                if (prog || i1 == 0) {
                    if (lane == 0) p[j1] = i;
                    if (i1 != 0 && prog) {
                        k--;
                        if (lane == 0) freelist[k] = i1;
                    }
                } else {
                    if (lane == 0) freelist[f] = i;
                    f++;
                }
                __syncwarp();
            }
            nf = f;
        }
    }
    // recompute free rows from p[] (robust to ARR early exit / budget)
    for (int x = lane; x <= N; x += 32) rowdone[x] = 0;
    __syncwarp();
    for (int j = 1 + lane; j <= N; j += 32) { int r = p[j]; if (r) rowdone[r] = 1; }
    __syncwarp();

    // ---- phase 3: shortest augmenting path for remaining free rows ----
    for (int i = 1; i <= N; i++) {
        if (rowdone[i]) continue;
        if (lane == 0) p[0] = i;
        usedmask = 0u;
        load_row12(C + (size_t)(i - 1) * N, jbase, c);
#pragma unroll
        for (int q = 0; q < 12; q++) {
            minv[q] = c[q] - v[q];                // u[i] = 0 for free rows
            way[1 + jbase + q] = 0;
        }
        __syncwarp();

        float dfin;
        int k;
        while (true) {
            // lane-local argmin over unused (ascending q == ascending j)
            float m = 3.0e38f; int bq = 0;
#pragma unroll
            for (int q = 0; q < 12; q++)
                if (!((usedmask >> q) & 1u) && minv[q] < m) { m = minv[q]; bq = q; }
            unsigned kmin = __reduce_min_sync(FULLW, fkey(m));
            unsigned ball = __ballot_sync(FULLW, fkey(m) == kmin);
            int src = __ffs(ball) - 1;                       // lowest lane == lowest j
            dfin = unfkey(kmin);                             // bit-exact popped distance
            k = __shfl_sync(FULLW, 1 + jbase + bq, src);
            if (lane == src) usedmask |= 1u << bq;
            int i0 = p[k];                                   // broadcast LDS
            if (i0 == 0) break;
            load_row12(C + (size_t)(i0 - 1) * N, jbase, c);
            // u[i0] = C[i0][k] - v[k]  (complementary slackness, src lane)
            float cv = 0.f;
#pragma unroll
            for (int q = 0; q < 12; q++)
                if (q == bq) cv = c[q] - v[q];
            float ui0 = __shfl_sync(FULLW, cv, src);
            float base = dfin - ui0;
#pragma unroll
            for (int q = 0; q < 12; q++) {
                if (!((usedmask >> q) & 1u)) {
                    float h = base + (c[q] - v[q]);
                    if (h < minv[q]) { minv[q] = h; way[1 + jbase + q] = k; }
                }
            }
        }
#pragma unroll
        for (int q = 0; q < 12; q++)
            if ((usedmask >> q) & 1u) v[q] += minv[q] - dfin;
        __syncwarp();
        if (lane == 0) {
            int jj = k;
            while (jj) { int j1 = way[jj]; p[jj] = p[j1]; jj = j1; }
        }
        __syncwarp();
    }
    for (int j = 1 + lane; j <= N; j += 32) g_assign[blockIdx.x][p[j] - 1] = j - 1;
}

// ---------------- finalize: hamming total + index outputs ----------------
__global__ void finalize_kernel(const void* permA, const void* permB, float* out) {
    __shared__ int idealcol[N];
    __shared__ int match[4];
    __shared__ int is64;
    int t = threadIdx.x;  // 384 threads
    if (t == 0) {
        const int* pa = (const int*)permA;
        int z = 1;
        for (int q = 1; q < 384; q += 2) if (pa[q] != 0) { z = 0; break; }
        is64 = z;
        match[0] = match[1] = match[2] = match[3] = 0;
    }
    __syncthreads();
    int a, b;
    if (is64) {
        a = (int)((const long long*)permA)[t];
        b = (int)((const long long*)permB)[t];
    } else {
        a = ((const int*)permA)[t];
        b = ((const int*)permB)[t];
    }
    idealcol[a] = b;
    __syncthreads();
    for (int l = 0; l < 4; l++)
        if (g_assign[l][t] == idealcol[t]) atomicAdd(&match[l], 1);
    __syncthreads();
    if (t == 0) {
        const float w[4] = {1.f, 0.5f, 0.25f, 0.125f};
        float total = 0.f;
        for (int l = 0; l < 4; l++)
            total += w[l] * (2.0f * (float)(N - match[l]) / (float)N);
        out[0] = total;
    }
    out[1 + t]     = (float)t;                  // row_ind
    out[1 + N + t] = (float)g_assign[4][t];     // col_ind from combined matrix
}

// ---------------- launch ----------------
extern "C" void kernel_launch(void* const* d_in, const int* in_sizes, int n_in,
                              void* d_out, int out_size) {
    const float* L[4] = {(const float*)d_in[0], (const float*)d_in[1],
                         (const float*)d_in[2], (const float*)d_in[3]};

    // layers 0,1 share d=16384 / nsplit=8; layers 2,3 share d=8192 / nsplit=4
    norm_kernel<<<dim3(2 * N, 2), 256>>>(L[0], L[1], 16384, 0);
    norm_kernel<<<dim3(2 * N, 2), 256>>>(L[2], L[3], 8192, 2);

    gemm_kernel<<<dim3(6, 6, 16), 256>>>(L[0], L[1], 16384, 8, 0);
    gemm_kernel<<<dim3(6, 6, 8),  256>>>(L[2], L[3], 8192, 4, 2);

    combine_kernel<<<(NN + 255) / 256, 256>>>();

    lap_kernel<<<NLAYER + 1, 32>>>();

    finalize_kernel<<<1, N>>>(d_in[4], d_in[5], (float*)d_out);
}

// round 15
// speedup vs baseline: 4.1877x; 1.0749x over previous
#include <cuda_runtime.h>

#define N 384
#define NN (N * N)
#define NLAYER 4
#define MAXSPLIT 8
#define KCHUNK 2048
#define FULLW 0xffffffffu

// ---------------- device scratch (no allocations allowed) ----------------
__device__ float g_partial[NLAYER][MAXSPLIT][NN];  // split-K partial dot products
__device__ float g_norm[NLAYER][2 * N];            // [l][0..383]=|a_i|^2, [l][384..767]=|b_j|^2
__device__ float g_cost[NLAYER + 1][NN];           // 4 layer costs + combined (index 4)
__device__ int   g_assign[NLAYER + 1][N];          // col_of_row per LAP problem

// ---------------- row norms: one block per row, grid.y = layer within pair ----------------
__global__ void norm_kernel(const float* __restrict__ base0, const float* __restrict__ base1,
                            int d, int layer0) {
    int row = blockIdx.x;  // 0..767 (A rows then B rows, contiguous in [2,N,d])
    const float* base = blockIdx.y ? base1 : base0;
    int layer = layer0 + blockIdx.y;
    const float* p = base + (size_t)row * d;
    float s = 0.f;
    int t = threadIdx.x;
    const float4* p4 = (const float4*)p;
    int n4 = d >> 2;
    for (int k = t; k < n4; k += 256) {
        float4 x = p4[k];
        s += x.x * x.x + x.y * x.y + x.z * x.z + x.w * x.w;
    }
    __shared__ float red[8];
    for (int o = 16; o; o >>= 1) s += __shfl_down_sync(FULLW, s, o);
    if ((t & 31) == 0) red[t >> 5] = s;
    __syncthreads();
    if (t < 8) {
        s = red[t];
        for (int o = 4; o; o >>= 1) s += __shfl_down_sync(0xffu, s, o);
        if (t == 0) g_norm[layer][row] = s;
    }
}

// ---------------- split-K NT GEMM: partial[s] = A_chunk @ B_chunk^T ----------------
// block: 256 threads, 64x64 tile, k-tile 16. grid (6, 6, nsplit*2): z = split + nsplit*pair_member
__global__ __launch_bounds__(256) void gemm_kernel(const float* __restrict__ L0,
                                                   const float* __restrict__ L1,
                                                   int d, int nsplit, int layer0) {
    __shared__ float As[16][64];
    __shared__ float Bs[16][64];
    int it = blockIdx.x * 64;
    int jt = blockIdx.y * 64;
    int zm = blockIdx.z / nsplit;      // 0 or 1: which layer of the pair
    int s  = blockIdx.z % nsplit;
    int layer = layer0 + zm;
    const float* Lbase = zm ? L1 : L0;
    const float* A = Lbase;
    const float* B = Lbase + (size_t)N * d;
    int kbase = s * KCHUNK;
    int t = threadIdx.x;
    int tx = t & 15, ty = t >> 4;

    float acc[4][4] = {};

    for (int kb = kbase; kb < kbase + KCHUNK; kb += 16) {
        __syncthreads();
#pragma unroll
        for (int e = 0; e < 4; e++) {
            int idx = t + e * 256;
            int li = idx >> 4, lk = idx & 15;
            As[lk][li] = A[(size_t)(it + li) * d + kb + lk];
            Bs[lk][li] = B[(size_t)(jt + li) * d + kb + lk];
        }
        __syncthreads();
#pragma unroll
        for (int kk = 0; kk < 16; kk++) {
            float4 a = *(const float4*)&As[kk][ty * 4];
            float4 b = *(const float4*)&Bs[kk][tx * 4];
            acc[0][0] += a.x * b.x; acc[0][1] += a.x * b.y; acc[0][2] += a.x * b.z; acc[0][3] += a.x * b.w;
            acc[1][0] += a.y * b.x; acc[1][1] += a.y * b.y; acc[1][2] += a.y * b.z; acc[1][3] += a.y * b.w;
            acc[2][0] += a.z * b.x; acc[2][1] += a.z * b.y; acc[2][2] += a.z * b.z; acc[2][3] += a.z * b.w;
            acc[3][0] += a.w * b.x; acc[3][1] += a.w * b.y; acc[3][2] += a.w * b.z; acc[3][3] += a.w * b.w;
        }
    }
    float* out = &g_partial[layer][s][0];
#pragma unroll
    for (int e = 0; e < 4; e++)
#pragma unroll
        for (int f = 0; f < 4; f++)
            out[(it + ty * 4 + e) * N + (jt + tx * 4 + f)] = acc[e][f];
}

// ---------------- epilogue: layer costs + combined ----------------
__global__ void combine_kernel() {
    int idx = blockIdx.x * blockDim.x + threadIdx.x;
    if (idx >= NN) return;
    int i = idx / N, j = idx % N;
    const float w[4]    = {1.f, 0.5f, 0.25f, 0.125f};
    const int nsplit[4] = {8, 8, 4, 4};
    const float invd[4] = {1.f / 16384.f, 1.f / 16384.f, 1.f / 8192.f, 1.f / 8192.f};
    float comb = 0.f;
#pragma unroll
    for (int l = 0; l < 4; l++) {
        float dot = 0.f;
        for (int ss = 0; ss < nsplit[l]; ss++) dot += g_partial[l][ss][idx];
        float sq = (g_norm[l][i] - 2.0f * dot) + g_norm[l][N + j];
        float c = fmaxf(sq, 0.f) * invd[l];
        g_cost[l][idx] = c;
        comb += w[l] * c;
    }
    g_cost[4][idx] = comb;
}

// order-preserving bijective float<->uint maps
__device__ __forceinline__ unsigned fkey(float x) {
    unsigned u = __float_as_uint(x);
    return u ^ (unsigned)(((int)u >> 31) | 0x80000000);
}
__device__ __forceinline__ float unfkey(unsigned k) {
    unsigned m = (unsigned)(~((int)k >> 31)) | 0x80000000u;
    return __uint_as_float(k ^ m);
}

// load 12 contiguous floats (48B, 16B-aligned) as 3 float4
__device__ __forceinline__ void load_row12(const float* __restrict__ Crow, int jbase, float c[12]) {
    const float4* r4 = (const float4*)(Crow + jbase);
    float4 a = r4[0], b = r4[1], d = r4[2];
    c[0] = a.x; c[1] = a.y; c[2]  = a.z; c[3]  = a.w;
    c[4] = b.x; c[5] = b.y; c[6]  = b.z; c[7]  = b.w;
    c[8] = d.x; c[9] = d.y; c[10] = d.z; c[11] = d.w;
}

// ---------------- warp-synchronous LAPJV (CR + RT + ARR + SAP), one warp/problem -----
// Lane owns 12 CONTIGUOUS columns j = 1 + 12*lane + q  (lowest tied lane == lowest j).
// ARR uses the canonical LAPJV always-assign rule (j1 is the row argmin, so the
// matched-column-achieves-row-min invariant holds with or without dual progress);
// a global budget bounds tie-cycles and the post-ARR free-row recompute keeps any
// early exit correct.
__global__ void lap_kernel() {
    const float* __restrict__ C = &g_cost[blockIdx.x][0];
    __shared__ int p[N + 1], way[N + 1];
    __shared__ int cmrow[N + 1];
    __shared__ int rowdone[N + 1];
    __shared__ int freelist[N];
    __shared__ int nf_sh;
    int lane = threadIdx.x;
    int jbase = lane * 12;

    float v[12], minv[12], c[12];
    unsigned usedmask;

    for (int j = lane; j <= N; j += 32) { p[j] = 0; rowdone[j] = 0; }
    __syncwarp();

    // ---- phase 1: column reduction ----
    int cmr[12];
#pragma unroll
    for (int q = 0; q < 12; q++) { v[q] = 3.0e38f; cmr[q] = 1; }
    for (int i = 1; i <= N; i++) {
        load_row12(C + (size_t)(i - 1) * N, jbase, c);
#pragma unroll
        for (int q = 0; q < 12; q++)
            if (c[q] < v[q]) { v[q] = c[q]; cmr[q] = i; }
    }
#pragma unroll
    for (int q = 0; q < 12; q++) cmrow[1 + jbase + q] = cmr[q];
    __syncwarp();
    if (lane == 0) {
        for (int j = 1; j <= N; j++) {
            int i = cmrow[j];
            if (!rowdone[i]) { rowdone[i] = 1; p[j] = i; }
        }
        int nf = 0;
        for (int i = 1; i <= N; i++) if (!rowdone[i]) freelist[nf++] = i;
        nf_sh = nf;
    }
    __syncwarp();

    // ---- phase 1b: reduction transfer (tighten v for assigned rows) ----
    // v_new[j] = C[i][j] - min_{j'!=j}(C[i][j'] - v[j']); keeps feasibility
    // (v only decreases) and complementary slackness equality at (i,j).
    for (int j = 1; j <= N; j++) {
        int i = p[j];  // uniform broadcast LDS
        if (i == 0) continue;
        load_row12(C + (size_t)(i - 1) * N, jbase, c);
        int ownerj = (j - 1) / 12, qj = (j - 1) % 12;
        float m = 3.0e38f;
#pragma unroll
        for (int q = 0; q < 12; q++) {
            float r = c[q] - v[q];
            if (!(lane == ownerj && q == qj) && r < m) m = r;
        }
        unsigned kmin = __reduce_min_sync(FULLW, fkey(m));
        float u2 = unfkey(kmin);
        if (lane == ownerj) {
#pragma unroll
            for (int q = 0; q < 12; q++)
                if (q == qj) v[q] = c[q] - u2;
        }
    }
    __syncwarp();

    // ---- phase 2: augmenting row reduction (canonical always-assign, budget-capped) ----
    {
        int nf = nf_sh;
        int budget = 3000;
        int k = 0;
        while (k < nf && budget > 0) {
            budget--;
            int i = freelist[k]; k++;
            load_row12(C + (size_t)(i - 1) * N, jbase, c);
            float m1 = 3.0e38f, m2 = 3.0e38f; int bq = 0;
#pragma unroll
            for (int q = 0; q < 12; q++) {
                float r = c[q] - v[q];
                if (r < m1) { m2 = m1; m1 = r; bq = q; }
                else if (r < m2) m2 = r;
            }
            unsigned k1 = __reduce_min_sync(FULLW, fkey(m1));
            unsigned ball = __ballot_sync(FULLW, fkey(m1) == k1);
            int src = __ffs(ball) - 1;                      // lowest lane == lowest j
            unsigned cand2 = (lane == src) ? fkey(m2) : fkey(m1);
            unsigned k2 = __reduce_min_sync(FULLW, cand2);
            float M1 = unfkey(k1), M2 = unfkey(k2);
            int j1 = __shfl_sync(FULLW, 1 + jbase + bq, src);
            int i1 = p[j1];                                 // read BEFORE write (program order)
            if (M1 < M2 && lane == src) {
#pragma unroll
                for (int q = 0; q < 12; q++)
                    if (q == bq) {
                        float nv = v[q] - (M2 - M1);
                        if (nv < v[q]) v[q] = nv;           // underflow-guarded tightening
                    }
            }
            if (lane == 0) p[j1] = i;                       // always assign (canonical LAPJV)
            if (i1 != 0) {
                k--;                                        // reprocess kicked row immediately
                if (lane == 0) freelist[k] = i1;
            }
            __syncwarp();
        }
    }
    // recompute free rows from p[] (robust to ARR budget exhaustion)
    for (int x = lane; x <= N; x += 32) rowdone[x] = 0;
    __syncwarp();
    for (int j = 1 + lane; j <= N; j += 32) { int r = p[j]; if (r) rowdone[r] = 1; }
    __syncwarp();

    // ---- phase 3: shortest augmenting path for remaining free rows ----
    for (int i = 1; i <= N; i++) {
        if (rowdone[i]) continue;
        if (lane == 0) p[0] = i;
        usedmask = 0u;
        load_row12(C + (size_t)(i - 1) * N, jbase, c);
        float m = 3.0e38f; int bq = 0;
#pragma unroll
        for (int q = 0; q < 12; q++) {
            minv[q] = c[q] - v[q];                // u[i] = 0 for free rows
            way[1 + jbase + q] = 0;
            if (minv[q] < m) { m = minv[q]; bq = q; }
        }
        __syncwarp();

        float dfin;
        int k;
        while (true) {
            unsigned kmin = __reduce_min_sync(FULLW, fkey(m));
            unsigned ball = __ballot_sync(FULLW, fkey(m) == kmin);
            int src = __ffs(ball) - 1;                       // lowest lane == lowest j
            dfin = unfkey(kmin);                             // bit-exact popped distance
            k = __shfl_sync(FULLW, 1 + jbase + bq, src);
            if (lane == src) usedmask |= 1u << bq;
            int i0 = p[k];                                   // broadcast LDS
            if (i0 == 0) break;
            load_row12(C + (size_t)(i0 - 1) * N, jbase, c);
            // u[i0] = C[i0][k] - v[k]  (complementary slackness, src lane)
            int bq0 = bq;
            float cv = 0.f;
#pragma unroll
            for (int q = 0; q < 12; q++)
                if (q == bq0) cv = c[q] - v[q];
            float ui0 = __shfl_sync(FULLW, cv, src);
            float base = dfin - ui0;
            // fused relax + lane-local argmin (ascending q == ascending j)
            m = 3.0e38f; bq = 0;
#pragma unroll
            for (int q = 0; q < 12; q++) {
                if (!((usedmask >> q) & 1u)) {
                    float h = base + (c[q] - v[q]);
                    if (h < minv[q]) { minv[q] = h; way[1 + jbase + q] = k; }
                    float mv = minv[q];
                    if (mv < m) { m = mv; bq = q; }
                }
            }
        }
#pragma unroll
        for (int q = 0; q < 12; q++)
            if ((usedmask >> q) & 1u) v[q] += minv[q] - dfin;
        __syncwarp();
        if (lane == 0) {
            int jj = k;
            while (jj) { int j1 = way[jj]; p[jj] = p[j1]; jj = j1; }
        }
        __syncwarp();
    }
    for (int j = 1 + lane; j <= N; j += 32) g_assign[blockIdx.x][p[j] - 1] = j - 1;
}

// ---------------- finalize: hamming total + index outputs ----------------
__global__ void finalize_kernel(const void* permA, const void* permB, float* out) {
    __shared__ int idealcol[N];
    __shared__ int match[4];
    __shared__ int is64;
    int t = threadIdx.x;  // 384 threads
    if (t == 0) {
        const int* pa = (const int*)permA;
        int z = 1;
        for (int q = 1; q < 384; q += 2) if (pa[q] != 0) { z = 0; break; }
        is64 = z;
        match[0] = match[1] = match[2] = match[3] = 0;
    }
    __syncthreads();
    int a, b;
    if (is64) {
        a = (int)((const long long*)permA)[t];
        b = (int)((const long long*)permB)[t];
    } else {
        a = ((const int*)permA)[t];
        b = ((const int*)permB)[t];
    }
    idealcol[a] = b;
    __syncthreads();
    for (int l = 0; l < 4; l++)
        if (g_assign[l][t] == idealcol[t]) atomicAdd(&match[l], 1);
    __syncthreads();
    if (t == 0) {
        const float w[4] = {1.f, 0.5f, 0.25f, 0.125f};
        float total = 0.f;
        for (int l = 0; l < 4; l++)
            total += w[l] * (2.0f * (float)(N - match[l]) / (float)N);
        out[0] = total;
    }
    out[1 + t]     = (float)t;                  // row_ind
    out[1 + N + t] = (float)g_assign[4][t];     // col_ind from combined matrix
}

// ---------------- launch ----------------
extern "C" void kernel_launch(void* const* d_in, const int* in_sizes, int n_in,
                              void* d_out, int out_size) {
    const float* L[4] = {(const float*)d_in[0], (const float*)d_in[1],
                         (const float*)d_in[2], (const float*)d_in[3]};

    // layers 0,1 share d=16384 / nsplit=8; layers 2,3 share d=8192 / nsplit=4
    norm_kernel<<<dim3(2 * N, 2), 256>>>(L[0], L[1], 16384, 0);
    norm_kernel<<<dim3(2 * N, 2), 256>>>(L[2], L[3], 8192, 2);

    gemm_kernel<<<dim3(6, 6, 16), 256>>>(L[0], L[1], 16384, 8, 0);
    gemm_kernel<<<dim3(6, 6, 8),  256>>>(L[2], L[3], 8192, 4, 2);

    combine_kernel<<<(NN + 255) / 256, 256>>>();

    lap_kernel<<<NLAYER + 1, 32>>>();

    finalize_kernel<<<1, N>>>(d_in[4], d_in[5], (float*)d_out);
}